// round 2
// baseline (speedup 1.0000x reference)
#include <cuda_runtime.h>
#include <cuda_bf16.h>
#include <stdint.h>

// Problem constants (TokenSelector: B=32, D=256, H=W=64)
#define BB 32
#define DD 256
#define NN 4096          // H*W
#define KK 2048          // NN * KEEP_RATIO

// ---------------- scratch (device globals; no allocation allowed) ----------
__device__ unsigned g_keys[BB * NN];   // monotone-sortable score keys
__device__ int      g_pos [BB * NN];   // output row per token, -1 if dropped

// float -> monotone-increasing uint key
__device__ __forceinline__ unsigned f2k(float f) {
    unsigned u = __float_as_uint(f);
    return u ^ ((u >> 31) ? 0xFFFFFFFFu : 0x80000000u);
}

// ---------------------------------------------------------------------------
// Kernel 1: per-token ordering key.  score = rstd*(dot(x,w') - mu*sum(w'))
// (softmax / norm_b / fc_b are order-irrelevant).  float4-vectorized: each
// thread handles 4 consecutive tokens; warp reads 512B contiguous per d.
// grid: (NN/(4*128)=8, BB), block: 128.
// ---------------------------------------------------------------------------
__global__ void __launch_bounds__(128)
score_kernel(const float* __restrict__ tokens,
             const float* __restrict__ norm_w,
             const float* __restrict__ fc_w,
             unsigned*    __restrict__ keys)
{
    __shared__ float wsh[DD];
    const int tid = threadIdx.x;
    wsh[tid]       = norm_w[tid]       * fc_w[tid];
    wsh[tid + 128] = norm_w[tid + 128] * fc_w[tid + 128];
    __syncthreads();

    const int b  = blockIdx.y;
    const int n4 = blockIdx.x * 128 + tid;          // float4-token index 0..1023
    const float4* p = (const float4*)(tokens + (size_t)b * DD * NN) + n4;

    float4 s1 = {0.f,0.f,0.f,0.f}, s2 = s1, sd = s1;
    float  sw = 0.f;
#pragma unroll 8
    for (int d = 0; d < DD; ++d) {
        float4 x = p[d * (NN / 4)];
        float  w = wsh[d];
        s1.x += x.x;       s1.y += x.y;       s1.z += x.z;       s1.w += x.w;
        s2.x += x.x*x.x;   s2.y += x.y*x.y;   s2.z += x.z*x.z;   s2.w += x.w*x.w;
        sd.x += x.x*w;     sd.y += x.y*w;     sd.z += x.z*w;     sd.w += x.w*w;
        sw   += w;
    }
    const float inv = 1.0f / (float)DD;
    uint4 kv;
    {
        float mu = s1.x*inv, var = fmaxf(s2.x*inv - mu*mu, 0.f);
        kv.x = f2k((sd.x - mu*sw) * rsqrtf(var + 1e-5f));
        mu = s1.y*inv; var = fmaxf(s2.y*inv - mu*mu, 0.f);
        kv.y = f2k((sd.y - mu*sw) * rsqrtf(var + 1e-5f));
        mu = s1.z*inv; var = fmaxf(s2.z*inv - mu*mu, 0.f);
        kv.z = f2k((sd.z - mu*sw) * rsqrtf(var + 1e-5f));
        mu = s1.w*inv; var = fmaxf(s2.w*inv - mu*mu, 0.f);
        kv.w = f2k((sd.w - mu*sw) * rsqrtf(var + 1e-5f));
    }
    ((uint4*)keys)[b * (NN / 4) + n4] = kv;
}

// ---------------------------------------------------------------------------
// Kernel 2: per-batch radix-select (KK-th largest) + rank compaction.
// One block per batch, 1024 threads, keys live in REGISTERS (uint4/thread).
// Warp-aggregated histogram atomics (__match_any_sync) kill the same-bin
// contention from concentrated float exponents. Bin selection is a parallel
// 256-wide suffix scan; compaction is a packed warp-shuffle scan.
// Tie semantics match jax.lax.top_k (lowest indices win at threshold).
// ---------------------------------------------------------------------------
__global__ void __launch_bounds__(1024)
select_kernel(const unsigned* __restrict__ keys, int* __restrict__ pos)
{
    __shared__ int hist[256];
    __shared__ int wsum[32];
    __shared__ unsigned s_prefix;
    __shared__ int s_R;

    const int tid  = threadIdx.x;
    const int lane = tid & 31;
    const int wid  = tid >> 5;
    const int b    = blockIdx.x;

    uint4 kv = ((const uint4*)(keys + b * NN))[tid];
    unsigned k[4] = {kv.x, kv.y, kv.z, kv.w};

    if (tid == 0) { s_prefix = 0u; s_R = KK; }
    __syncthreads();

    unsigned mask = 0u;
    for (int shift = 24; shift >= 0; shift -= 8) {
        if (tid < 256) hist[tid] = 0;
        __syncthreads();
        const unsigned prefix = s_prefix;
        const int      R      = s_R;

        // warp-aggregated histogram
#pragma unroll
        for (int j = 0; j < 4; ++j) {
            int bin = ((k[j] & mask) == prefix) ? (int)((k[j] >> shift) & 255u) : 256;
            unsigned mm  = __match_any_sync(0xFFFFFFFFu, bin);
            int      ldr = __ffs(mm) - 1;
            if (lane == ldr && bin < 256)
                atomicAdd(&hist[bin], __popc(mm));
        }
        __syncthreads();

        // suffix count S(bin) = #keys with bin' >= bin (within prefix class),
        // computed as inclusive prefix over r = 255 - bin.
        if (tid < 256) {
            int c = hist[255 - tid];
            int v = c;
#pragma unroll
            for (int o = 1; o < 32; o <<= 1) {
                int t = __shfl_up_sync(0xFFFFFFFFu, v, o);
                if (lane >= o) v += t;
            }
            if (lane == 31) wsum[wid] = v;      // wid 0..7
            // stash (v, c) in registers across the barrier
            __syncthreads();
            int S = v;
#pragma unroll
            for (int w = 0; w < 7; ++w)
                if (w < wid) S += wsum[w];
            if (S >= R && S - c < R) {          // unique boundary thread
                s_prefix = prefix | ((unsigned)(255 - tid) << shift);
                s_R      = R - (S - c);
            }
        } else {
            __syncthreads();
        }
        mask |= 255u << shift;
        __syncthreads();
    }
    const unsigned T    = s_prefix;   // threshold key (KK-th largest)
    const int      Rfin = s_R;        // # of ==T keys kept (lowest index first)

    // rank compaction: packed (countGT<<16 | countEQ) scan over 1024 threads
    int cg = 0, ce = 0;
#pragma unroll
    for (int j = 0; j < 4; ++j) { cg += (k[j] > T); ce += (k[j] == T); }
    int myv = (cg << 16) | ce;
    int v = myv;
#pragma unroll
    for (int o = 1; o < 32; o <<= 1) {
        int t = __shfl_up_sync(0xFFFFFFFFu, v, o);
        if (lane >= o) v += t;
    }
    if (lane == 31) wsum[wid] = v;
    __syncthreads();
    if (wid == 0) {
        int t = wsum[lane];
#pragma unroll
        for (int o = 1; o < 32; o <<= 1) {
            int u = __shfl_up_sync(0xFFFFFFFFu, t, o);
            if (lane >= o) t += u;
        }
        wsum[lane] = t;
    }
    __syncthreads();
    int pre = v - myv + (wid > 0 ? wsum[wid - 1] : 0);  // exclusive prefix
    int g = pre >> 16;
    int e = pre & 0xFFFF;

    int4 op;
    int vals[4];
#pragma unroll
    for (int j = 0; j < 4; ++j) {
        int kp = -1;
        if (k[j] > T)       { kp = g + min(e, Rfin); ++g; }
        else if (k[j] == T) { if (e < Rfin) kp = g + e; ++e; }
        vals[j] = kp;
    }
    op.x = vals[0]; op.y = vals[1]; op.z = vals[2]; op.w = vals[3];
    ((int4*)(pos + b * NN))[tid] = op;
}

// ---------------------------------------------------------------------------
// Kernel 3: streaming compaction-gather with smem transpose (conflict-free).
// Batch order REVERSED so the batches score_kernel touched last (still hot in
// the 126MB L2) are read first.
// grid: (NN/32, BB), block: 256 (8 warps).
// ---------------------------------------------------------------------------
__global__ void __launch_bounds__(256)
gather_kernel(const float* __restrict__ tokens,
              const int* __restrict__ pos,
              float* __restrict__ out)
{
    __shared__ float tile[32][DD + 1];   // +1 pad: conflict-free transpose
    __shared__ int   spos[32];

    const int tid  = threadIdx.x;
    const int lane = tid & 31;
    const int wid  = tid >> 5;           // 0..7
    const int b    = (BB - 1) - blockIdx.y;   // hottest-in-L2 batches first
    const int n0   = blockIdx.x * 32;

    if (tid < 32) spos[tid] = pos[b * NN + n0 + tid];

    const float* base = tokens + (size_t)b * DD * NN + n0 + lane;
#pragma unroll
    for (int j = 0; j < 32; ++j) {
        int d = wid + j * 8;
        tile[lane][d] = base[(size_t)d * NN];
    }
    __syncthreads();

    float* ob = out + (size_t)b * KK * DD;
#pragma unroll 4
    for (int kk = 0; kk < 32; ++kk) {
        int p = spos[kk];
        if (p >= 0) ob[(size_t)p * DD + tid] = tile[kk][tid];
    }
}

// ---------------------------------------------------------------------------
extern "C" void kernel_launch(void* const* d_in, const int* in_sizes, int n_in,
                              void* d_out, int out_size)
{
    const float* tokens = (const float*)d_in[0];
    const float* norm_w = (const float*)d_in[1];
    // d_in[2] = norm_b (order-irrelevant constant shift)
    const float* fc_w   = (const float*)d_in[3];
    // d_in[4] = fc_b   (order-irrelevant constant shift)
    float* out = (float*)d_out;

    unsigned* keys;
    int* pos;
    cudaGetSymbolAddress((void**)&keys, g_keys);
    cudaGetSymbolAddress((void**)&pos,  g_pos);

    score_kernel<<<dim3(NN / 512, BB), 128>>>(tokens, norm_w, fc_w, keys);
    select_kernel<<<BB, 1024>>>(keys, pos);
    gather_kernel<<<dim3(NN / 32, BB), 256>>>(tokens, pos, out);
}

// round 3
// speedup vs baseline: 1.3806x; 1.3806x over previous
#include <cuda_runtime.h>
#include <cuda_bf16.h>
#include <stdint.h>

// Problem constants (TokenSelector: B=32, D=256, H=W=64)
#define BB 32
#define DD 256
#define NN 4096          // H*W
#define KK 2048          // NN * KEEP_RATIO

// ---------------- scratch (device globals; no allocation allowed) ----------
__device__ unsigned g_keys[BB * NN];   // monotone-sortable score keys
__device__ int      g_pos [BB * NN];   // output row per token, -1 if dropped

// float -> monotone-increasing uint key
__device__ __forceinline__ unsigned f2k(float f) {
    unsigned u = __float_as_uint(f);
    return u ^ ((u >> 31) ? 0xFFFFFFFFu : 0x80000000u);
}

// ---------------------------------------------------------------------------
// Kernel 1: per-token ordering key.  score = rstd*(dot(x,w') - mu*sum(w'))
// (softmax / norm_b / fc_b are order-irrelevant).
// Thread-per-token (proven R1 layout: warp reads 128B contiguous per d),
// with explicit 16-deep load batching for MLP=16 (~53KB in flight/SM).
// grid: (NN/256=16, BB) = 512 blocks, block 256.
// ---------------------------------------------------------------------------
__global__ void __launch_bounds__(256)
score_kernel(const float* __restrict__ tokens,
             const float* __restrict__ norm_w,
             const float* __restrict__ fc_w,
             unsigned*    __restrict__ keys)
{
    __shared__ float wsh[DD];
    const int tid = threadIdx.x;
    wsh[tid] = norm_w[tid] * fc_w[tid];
    __syncthreads();

    const int b = blockIdx.y;
    const int n = blockIdx.x * 256 + tid;
    const float* p = tokens + (size_t)b * DD * NN + n;

    float s1 = 0.f, s2 = 0.f, sd = 0.f, sw = 0.f;
    for (int d0 = 0; d0 < DD; d0 += 16) {
        float x[16];
#pragma unroll
        for (int j = 0; j < 16; ++j)           // 16 independent LDGs, front-batched
            x[j] = p[(size_t)(d0 + j) * NN];
#pragma unroll
        for (int j = 0; j < 16; ++j) {
            float w = wsh[d0 + j];
            s1 += x[j];
            s2 += x[j] * x[j];
            sd += x[j] * w;
            sw += w;
        }
    }
    const float inv = 1.0f / (float)DD;
    float mu   = s1 * inv;
    float var  = fmaxf(s2 * inv - mu * mu, 0.f);
    float rstd = rsqrtf(var + 1e-5f);
    keys[b * NN + n] = f2k((sd - mu * sw) * rstd);
}

// ---------------------------------------------------------------------------
// Kernel 2: per-batch radix-select (KK-th largest) + rank compaction.
// One block per batch, 1024 threads, keys in registers (uint4/thread).
// Warp-aggregated histogram atomics; parallel suffix-scan bin pick;
// packed warp-shuffle scan compaction. Ties: lowest indices win (lax.top_k).
// ---------------------------------------------------------------------------
__global__ void __launch_bounds__(1024)
select_kernel(const unsigned* __restrict__ keys, int* __restrict__ pos)
{
    __shared__ int hist[256];
    __shared__ int wsum[32];
    __shared__ unsigned s_prefix;
    __shared__ int s_R;

    const int tid  = threadIdx.x;
    const int lane = tid & 31;
    const int wid  = tid >> 5;
    const int b    = blockIdx.x;

    uint4 kv = ((const uint4*)(keys + b * NN))[tid];
    unsigned k[4] = {kv.x, kv.y, kv.z, kv.w};

    if (tid == 0) { s_prefix = 0u; s_R = KK; }
    __syncthreads();

    unsigned mask = 0u;
    for (int shift = 24; shift >= 0; shift -= 8) {
        if (tid < 256) hist[tid] = 0;
        __syncthreads();
        const unsigned prefix = s_prefix;
        const int      R      = s_R;

#pragma unroll
        for (int j = 0; j < 4; ++j) {
            int bin = ((k[j] & mask) == prefix) ? (int)((k[j] >> shift) & 255u) : 256;
            unsigned mm  = __match_any_sync(0xFFFFFFFFu, bin);
            int      ldr = __ffs(mm) - 1;
            if (lane == ldr && bin < 256)
                atomicAdd(&hist[bin], __popc(mm));
        }
        __syncthreads();

        if (tid < 256) {
            int c = hist[255 - tid];
            int v = c;
#pragma unroll
            for (int o = 1; o < 32; o <<= 1) {
                int t = __shfl_up_sync(0xFFFFFFFFu, v, o);
                if (lane >= o) v += t;
            }
            if (lane == 31) wsum[wid] = v;
            __syncthreads();
            int S = v;
#pragma unroll
            for (int w = 0; w < 7; ++w)
                if (w < wid) S += wsum[w];
            if (S >= R && S - c < R) {           // unique boundary thread
                s_prefix = prefix | ((unsigned)(255 - tid) << shift);
                s_R      = R - (S - c);
            }
        } else {
            __syncthreads();
        }
        mask |= 255u << shift;
        __syncthreads();
    }
    const unsigned T    = s_prefix;
    const int      Rfin = s_R;

    int cg = 0, ce = 0;
#pragma unroll
    for (int j = 0; j < 4; ++j) { cg += (k[j] > T); ce += (k[j] == T); }
    int myv = (cg << 16) | ce;
    int v = myv;
#pragma unroll
    for (int o = 1; o < 32; o <<= 1) {
        int t = __shfl_up_sync(0xFFFFFFFFu, v, o);
        if (lane >= o) v += t;
    }
    if (lane == 31) wsum[wid] = v;
    __syncthreads();
    if (wid == 0) {
        int t = wsum[lane];
#pragma unroll
        for (int o = 1; o < 32; o <<= 1) {
            int u = __shfl_up_sync(0xFFFFFFFFu, t, o);
            if (lane >= o) t += u;
        }
        wsum[lane] = t;
    }
    __syncthreads();
    int pre = v - myv + (wid > 0 ? wsum[wid - 1] : 0);
    int g = pre >> 16;
    int e = pre & 0xFFFF;

    int vals[4];
#pragma unroll
    for (int j = 0; j < 4; ++j) {
        int kp = -1;
        if (k[j] > T)       { kp = g + min(e, Rfin); ++g; }
        else if (k[j] == T) { if (e < Rfin) kp = g + e; ++e; }
        vals[j] = kp;
    }
    int4 op = { vals[0], vals[1], vals[2], vals[3] };
    ((int4*)(pos + b * NN))[tid] = op;
}

// ---------------------------------------------------------------------------
// Kernel 3: streaming compaction-gather, float4 loads + [d][n] smem tile.
// Block covers 32 source tokens x D=256. Loads: each thread does 8 float4
// LDGs (128B in flight), fully coalesced. tile[256][33]: float4 stores land
// in distinct banks; column reads (fixed kk, d=tid) stride 33 -> conflict-free.
// Kept rows written as contiguous 1KB lines. Batch order reversed for L2 hits.
// grid: (NN/32, BB), block 256.
// ---------------------------------------------------------------------------
__global__ void __launch_bounds__(256)
gather_kernel(const float* __restrict__ tokens,
              const int* __restrict__ pos,
              float* __restrict__ out)
{
    __shared__ float tile[DD][33];       // [d][n], pad 33: conflict-free both ways
    __shared__ int   spos[32];

    const int tid = threadIdx.x;
    const int b   = (BB - 1) - blockIdx.y;    // hottest-in-L2 batches first
    const int n0  = blockIdx.x * 32;

    if (tid < 32) spos[tid] = pos[b * NN + n0 + tid];

    const int f  = tid & 7;              // float4 slot within 32-token row
    const int d0 = tid >> 3;             // 0..31
    const float* base = tokens + (size_t)b * DD * NN + n0 + f * 4;
#pragma unroll
    for (int j = 0; j < 8; ++j) {        // 8 independent 16B LDGs
        int d = d0 + j * 32;
        float4 v = *(const float4*)(base + (size_t)d * NN);
        tile[d][f * 4 + 0] = v.x;
        tile[d][f * 4 + 1] = v.y;
        tile[d][f * 4 + 2] = v.z;
        tile[d][f * 4 + 3] = v.w;
    }
    __syncthreads();

    float* ob = out + (size_t)b * KK * DD;
#pragma unroll 4
    for (int kk = 0; kk < 32; ++kk) {
        int p = spos[kk];
        if (p >= 0) ob[(size_t)p * DD + tid] = tile[tid][kk];
    }
}

// ---------------------------------------------------------------------------
extern "C" void kernel_launch(void* const* d_in, const int* in_sizes, int n_in,
                              void* d_out, int out_size)
{
    const float* tokens = (const float*)d_in[0];
    const float* norm_w = (const float*)d_in[1];
    // d_in[2] = norm_b (order-irrelevant constant shift)
    const float* fc_w   = (const float*)d_in[3];
    // d_in[4] = fc_b   (order-irrelevant constant shift)
    float* out = (float*)d_out;

    unsigned* keys;
    int* pos;
    cudaGetSymbolAddress((void**)&keys, g_keys);
    cudaGetSymbolAddress((void**)&pos,  g_pos);

    score_kernel<<<dim3(NN / 256, BB), 256>>>(tokens, norm_w, fc_w, keys);
    select_kernel<<<BB, 1024>>>(keys, pos);
    gather_kernel<<<dim3(NN / 32, BB), 256>>>(tokens, pos, out);
}

// round 4
// speedup vs baseline: 1.5633x; 1.1323x over previous
#include <cuda_runtime.h>
#include <cuda_bf16.h>
#include <stdint.h>

// Problem constants (TokenSelector: B=32, D=256, H=W=64)
#define BB 32
#define DD 256
#define NN 4096          // H*W
#define KK 2048          // NN * KEEP_RATIO

// ---------------- scratch (device globals; no allocation allowed) ----------
__device__ unsigned g_keys[BB * NN];   // monotone-sortable score keys
__device__ int      g_pos [BB * NN];   // output row per token, -1 if dropped

// float -> monotone-increasing uint key
__device__ __forceinline__ unsigned f2k(float f) {
    unsigned u = __float_as_uint(f);
    return u ^ ((u >> 31) ? 0xFFFFFFFFu : 0x80000000u);
}

// ---------------------------------------------------------------------------
// Kernel 1: per-token ordering key.  score = rstd*(dot(x,w') - mu*sum(w'))
// (softmax / norm_b / fc_b are order-irrelevant).
// TWO threads per token (each covers 128 of the 256 d's) -> 8192 warps total
// (~55 warps/SM, vs 27.7 at 1 thread/token). Warp reads 128B contiguous/d.
// grid: (NN/128=32, BB) = 1024 blocks, block 256.
// ---------------------------------------------------------------------------
__global__ void __launch_bounds__(256)
score_kernel(const float* __restrict__ tokens,
             const float* __restrict__ norm_w,
             const float* __restrict__ fc_w,
             unsigned*    __restrict__ keys)
{
    __shared__ float wsh[DD];
    __shared__ float a1[128], a2[128], a3[128], a4[128];

    const int tid = threadIdx.x;
    wsh[tid] = norm_w[tid] * fc_w[tid];
    __syncthreads();

    const int b    = blockIdx.y;
    const int q    = tid & 127;          // token slot within block
    const int half = tid >> 7;           // d-half: 0 or 1
    const int n    = blockIdx.x * 128 + q;
    const float* p = tokens + (size_t)b * DD * NN + (size_t)(half * 128) * NN + n;

    float s1 = 0.f, s2 = 0.f, sd = 0.f, sw = 0.f;
    for (int d0 = 0; d0 < 128; d0 += 8) {
        float x[8];
#pragma unroll
        for (int j = 0; j < 8; ++j)          // 8 independent LDGs in flight
            x[j] = p[(size_t)(d0 + j) * NN];
#pragma unroll
        for (int j = 0; j < 8; ++j) {
            float w = wsh[half * 128 + d0 + j];
            s1 += x[j];
            s2 += x[j] * x[j];
            sd += x[j] * w;
            sw += w;
        }
    }
    if (half) { a1[q] = s1; a2[q] = s2; a3[q] = sd; a4[q] = sw; }
    __syncthreads();
    if (!half) {
        s1 += a1[q]; s2 += a2[q]; sd += a3[q]; sw += a4[q];
        const float inv = 1.0f / (float)DD;
        float mu   = s1 * inv;
        float var  = fmaxf(s2 * inv - mu * mu, 0.f);
        float rstd = rsqrtf(var + 1e-5f);
        keys[b * NN + n] = f2k((sd - mu * sw) * rstd);
    }
}

// ---------------------------------------------------------------------------
// Kernel 2: per-batch radix-select (KK-th largest) + rank compaction.
// One block per batch, 1024 threads, keys in registers (uint4/thread).
// Warp-aggregated histogram atomics; parallel suffix-scan bin pick;
// packed warp-shuffle scan compaction. Ties: lowest indices win (lax.top_k).
// ---------------------------------------------------------------------------
__global__ void __launch_bounds__(1024)
select_kernel(const unsigned* __restrict__ keys, int* __restrict__ pos)
{
    __shared__ int hist[256];
    __shared__ int wsum[32];
    __shared__ unsigned s_prefix;
    __shared__ int s_R;

    const int tid  = threadIdx.x;
    const int lane = tid & 31;
    const int wid  = tid >> 5;
    const int b    = blockIdx.x;

    uint4 kv = ((const uint4*)(keys + b * NN))[tid];
    unsigned k[4] = {kv.x, kv.y, kv.z, kv.w};

    if (tid == 0) { s_prefix = 0u; s_R = KK; }
    __syncthreads();

    unsigned mask = 0u;
    for (int shift = 24; shift >= 0; shift -= 8) {
        if (tid < 256) hist[tid] = 0;
        __syncthreads();
        const unsigned prefix = s_prefix;
        const int      R      = s_R;

#pragma unroll
        for (int j = 0; j < 4; ++j) {
            int bin = ((k[j] & mask) == prefix) ? (int)((k[j] >> shift) & 255u) : 256;
            unsigned mm  = __match_any_sync(0xFFFFFFFFu, bin);
            int      ldr = __ffs(mm) - 1;
            if (lane == ldr && bin < 256)
                atomicAdd(&hist[bin], __popc(mm));
        }
        __syncthreads();

        if (tid < 256) {
            int c = hist[255 - tid];
            int v = c;
#pragma unroll
            for (int o = 1; o < 32; o <<= 1) {
                int t = __shfl_up_sync(0xFFFFFFFFu, v, o);
                if (lane >= o) v += t;
            }
            if (lane == 31) wsum[wid] = v;
            __syncthreads();
            int S = v;
#pragma unroll
            for (int w = 0; w < 7; ++w)
                if (w < wid) S += wsum[w];
            if (S >= R && S - c < R) {           // unique boundary thread
                s_prefix = prefix | ((unsigned)(255 - tid) << shift);
                s_R      = R - (S - c);
            }
        } else {
            __syncthreads();
        }
        mask |= 255u << shift;
        __syncthreads();
    }
    const unsigned T    = s_prefix;
    const int      Rfin = s_R;

    int cg = 0, ce = 0;
#pragma unroll
    for (int j = 0; j < 4; ++j) { cg += (k[j] > T); ce += (k[j] == T); }
    int myv = (cg << 16) | ce;
    int v = myv;
#pragma unroll
    for (int o = 1; o < 32; o <<= 1) {
        int t = __shfl_up_sync(0xFFFFFFFFu, v, o);
        if (lane >= o) v += t;
    }
    if (lane == 31) wsum[wid] = v;
    __syncthreads();
    if (wid == 0) {
        int t = wsum[lane];
#pragma unroll
        for (int o = 1; o < 32; o <<= 1) {
            int u = __shfl_up_sync(0xFFFFFFFFu, t, o);
            if (lane >= o) t += u;
        }
        wsum[lane] = t;
    }
    __syncthreads();
    int pre = v - myv + (wid > 0 ? wsum[wid - 1] : 0);
    int g = pre >> 16;
    int e = pre & 0xFFFF;

    int vals[4];
#pragma unroll
    for (int j = 0; j < 4; ++j) {
        int kp = -1;
        if (k[j] > T)       { kp = g + min(e, Rfin); ++g; }
        else if (k[j] == T) { if (e < Rfin) kp = g + e; ++e; }
        vals[j] = kp;
    }
    int4 op = { vals[0], vals[1], vals[2], vals[3] };
    ((int4*)(pos + b * NN))[tid] = op;
}

// ---------------------------------------------------------------------------
// Kernel 3: streaming compaction-gather. 32 tokens x D, processed in TWO
// d-halves so the smem tile is only 128x33 floats (17KB -> 64 warps/SM,
// vs 132KB/1-block/SM before). float4 loads, conflict-free smem both ways
// ((33d + c) mod 32 == d + c). Kept rows written as contiguous 512B halves.
// Batch order reversed so score's L2-hot batches are read first.
// grid: (NN/32=128, BB), block 256.
// ---------------------------------------------------------------------------
__global__ void __launch_bounds__(256)
gather_kernel(const float* __restrict__ tokens,
              const int* __restrict__ pos,
              float* __restrict__ out)
{
    __shared__ float tile[128][33];
    __shared__ int   spos[32];

    const int tid = threadIdx.x;
    const int b   = (BB - 1) - blockIdx.y;    // hottest-in-L2 batches first
    const int n0  = blockIdx.x * 32;

    if (tid < 32) spos[tid] = pos[b * NN + n0 + tid];

    const int f  = tid & 7;                   // float4 slot (4 tokens)
    const int d0 = tid >> 3;                  // 0..31
    const float* base = tokens + (size_t)b * DD * NN + n0 + f * 4;
    float* ob = out + (size_t)b * KK * DD;

    const int kk2 = tid >> 7;                 // which of 2 rows this thread writes
    const int c   = tid & 127;                // column within 128-wide half

#pragma unroll
    for (int h = 0; h < 2; ++h) {
        __syncthreads();                      // tile reuse guard (and spos vis)
#pragma unroll
        for (int j = 0; j < 4; ++j) {         // 4 independent 16B LDGs
            int d = d0 + j * 32;              // local d within half
            float4 v = *(const float4*)(base + (size_t)(h * 128 + d) * NN);
            tile[d][f * 4 + 0] = v.x;
            tile[d][f * 4 + 1] = v.y;
            tile[d][f * 4 + 2] = v.z;
            tile[d][f * 4 + 3] = v.w;
        }
        __syncthreads();
#pragma unroll
        for (int pair = 0; pair < 16; ++pair) {
            int kk = pair * 2 + kk2;
            int p  = spos[kk];
            if (p >= 0) ob[(size_t)p * DD + h * 128 + c] = tile[c][kk];
        }
    }
}

// ---------------------------------------------------------------------------
extern "C" void kernel_launch(void* const* d_in, const int* in_sizes, int n_in,
                              void* d_out, int out_size)
{
    const float* tokens = (const float*)d_in[0];
    const float* norm_w = (const float*)d_in[1];
    // d_in[2] = norm_b (order-irrelevant constant shift)
    const float* fc_w   = (const float*)d_in[3];
    // d_in[4] = fc_b   (order-irrelevant constant shift)
    float* out = (float*)d_out;

    unsigned* keys;
    int* pos;
    cudaGetSymbolAddress((void**)&keys, g_keys);
    cudaGetSymbolAddress((void**)&pos,  g_pos);

    score_kernel<<<dim3(NN / 128, BB), 256>>>(tokens, norm_w, fc_w, keys);
    select_kernel<<<BB, 1024>>>(keys, pos);
    gather_kernel<<<dim3(NN / 32, BB), 256>>>(tokens, pos, out);
}

// round 5
// speedup vs baseline: 1.6731x; 1.0702x over previous
#include <cuda_runtime.h>
#include <cuda_bf16.h>
#include <stdint.h>

// Problem constants (TokenSelector: B=32, D=256, H=W=64)
#define BB 32
#define DD 256
#define NN 4096          // H*W
#define KK 2048          // NN * KEEP_RATIO

// ---------------- scratch (device globals; no allocation allowed) ----------
__device__ unsigned g_keys[BB * NN];   // monotone-sortable score keys
__device__ int      g_pos [BB * NN];   // output row per token, -1 if dropped

// float -> monotone-increasing uint key
__device__ __forceinline__ unsigned f2k(float f) {
    unsigned u = __float_as_uint(f);
    return u ^ ((u >> 31) ? 0xFFFFFFFFu : 0x80000000u);
}

// ---------------------------------------------------------------------------
// Kernel 1: per-token ordering key.  score = rstd*(dot(x,w') - mu*sum(w'))
// (softmax / norm_b / fc_b are order-irrelevant).
// float4 layout: thread owns a QUAD of 4 consecutive tokens over a 32-wide
// d-slice. Warp = one d-slice x 32 quads -> 512B contiguous per LDG.128.
// 8 d-slices reduced via smem. grid (NN/128=32, BB)=1024 blocks, block 256
// (~55 warps/SM), ~2KB in flight per warp.
// ---------------------------------------------------------------------------
__global__ void __launch_bounds__(256)
score_kernel(const float* __restrict__ tokens,
             const float* __restrict__ norm_w,
             const float* __restrict__ fc_w,
             unsigned*    __restrict__ keys)
{
    __shared__ float  wsh[DD];
    __shared__ float4 r1[8][32], r2[8][32], r3[8][32];
    __shared__ float  rw[8][32];

    const int tid   = threadIdx.x;
    const int q     = tid & 31;     // token-quad slot within block
    const int split = tid >> 5;     // d-slice 0..7 (32 d's each)

    wsh[tid] = norm_w[tid] * fc_w[tid];
    __syncthreads();

    const int b  = blockIdx.y;
    const int n4 = blockIdx.x * 32 + q;            // quad index 0..1023
    const float4* p = (const float4*)(tokens + (size_t)b * DD * NN) + n4;

    float4 s1 = {0.f,0.f,0.f,0.f}, s2 = s1, sd = s1;
    float  sw = 0.f;
#pragma unroll
    for (int j0 = 0; j0 < 32; j0 += 4) {
        float4 x[4];
#pragma unroll
        for (int jj = 0; jj < 4; ++jj)             // 4 independent 16B LDGs
            x[jj] = p[(size_t)(split * 32 + j0 + jj) * (NN / 4)];
#pragma unroll
        for (int jj = 0; jj < 4; ++jj) {
            float w = wsh[split * 32 + j0 + jj];
            s1.x += x[jj].x;          s1.y += x[jj].y;
            s1.z += x[jj].z;          s1.w += x[jj].w;
            s2.x += x[jj].x * x[jj].x; s2.y += x[jj].y * x[jj].y;
            s2.z += x[jj].z * x[jj].z; s2.w += x[jj].w * x[jj].w;
            sd.x += x[jj].x * w;       sd.y += x[jj].y * w;
            sd.z += x[jj].z * w;       sd.w += x[jj].w * w;
            sw   += w;
        }
    }
    r1[split][q] = s1; r2[split][q] = s2; r3[split][q] = sd; rw[split][q] = sw;
    __syncthreads();

    if (split == 0) {                               // one warp finalizes 32 quads
#pragma unroll
        for (int s = 1; s < 8; ++s) {
            float4 a = r1[s][q], c = r2[s][q], d = r3[s][q];
            s1.x += a.x; s1.y += a.y; s1.z += a.z; s1.w += a.w;
            s2.x += c.x; s2.y += c.y; s2.z += c.z; s2.w += c.w;
            sd.x += d.x; sd.y += d.y; sd.z += d.z; sd.w += d.w;
            sw   += rw[s][q];
        }
        const float inv = 1.0f / (float)DD;
        uint4 kv;
        float mu, var;
        mu = s1.x*inv; var = fmaxf(s2.x*inv - mu*mu, 0.f);
        kv.x = f2k((sd.x - mu*sw) * rsqrtf(var + 1e-5f));
        mu = s1.y*inv; var = fmaxf(s2.y*inv - mu*mu, 0.f);
        kv.y = f2k((sd.y - mu*sw) * rsqrtf(var + 1e-5f));
        mu = s1.z*inv; var = fmaxf(s2.z*inv - mu*mu, 0.f);
        kv.z = f2k((sd.z - mu*sw) * rsqrtf(var + 1e-5f));
        mu = s1.w*inv; var = fmaxf(s2.w*inv - mu*mu, 0.f);
        kv.w = f2k((sd.w - mu*sw) * rsqrtf(var + 1e-5f));
        ((uint4*)keys)[b * (NN / 4) + n4] = kv;
    }
}

// ---------------------------------------------------------------------------
// Kernel 2: per-batch radix-select (KK-th largest) + rank compaction.
// One block per batch, 1024 threads, keys in registers (uint4/thread).
// Warp-aggregated histogram atomics; parallel suffix-scan bin pick;
// packed warp-shuffle scan compaction. Ties: lowest indices win (lax.top_k).
// ---------------------------------------------------------------------------
__global__ void __launch_bounds__(1024)
select_kernel(const unsigned* __restrict__ keys, int* __restrict__ pos)
{
    __shared__ int hist[256];
    __shared__ int wsum[32];
    __shared__ unsigned s_prefix;
    __shared__ int s_R;

    const int tid  = threadIdx.x;
    const int lane = tid & 31;
    const int wid  = tid >> 5;
    const int b    = blockIdx.x;

    uint4 kv = ((const uint4*)(keys + b * NN))[tid];
    unsigned k[4] = {kv.x, kv.y, kv.z, kv.w};

    if (tid == 0) { s_prefix = 0u; s_R = KK; }
    __syncthreads();

    unsigned mask = 0u;
    for (int shift = 24; shift >= 0; shift -= 8) {
        if (tid < 256) hist[tid] = 0;
        __syncthreads();
        const unsigned prefix = s_prefix;
        const int      R      = s_R;

#pragma unroll
        for (int j = 0; j < 4; ++j) {
            int bin = ((k[j] & mask) == prefix) ? (int)((k[j] >> shift) & 255u) : 256;
            unsigned mm  = __match_any_sync(0xFFFFFFFFu, bin);
            int      ldr = __ffs(mm) - 1;
            if (lane == ldr && bin < 256)
                atomicAdd(&hist[bin], __popc(mm));
        }
        __syncthreads();

        if (tid < 256) {
            int c = hist[255 - tid];
            int v = c;
#pragma unroll
            for (int o = 1; o < 32; o <<= 1) {
                int t = __shfl_up_sync(0xFFFFFFFFu, v, o);
                if (lane >= o) v += t;
            }
            if (lane == 31) wsum[wid] = v;
            __syncthreads();
            int S = v;
#pragma unroll
            for (int w = 0; w < 7; ++w)
                if (w < wid) S += wsum[w];
            if (S >= R && S - c < R) {           // unique boundary thread
                s_prefix = prefix | ((unsigned)(255 - tid) << shift);
                s_R      = R - (S - c);
            }
        } else {
            __syncthreads();
        }
        mask |= 255u << shift;
        __syncthreads();
    }
    const unsigned T    = s_prefix;
    const int      Rfin = s_R;

    int cg = 0, ce = 0;
#pragma unroll
    for (int j = 0; j < 4; ++j) { cg += (k[j] > T); ce += (k[j] == T); }
    int myv = (cg << 16) | ce;
    int v = myv;
#pragma unroll
    for (int o = 1; o < 32; o <<= 1) {
        int t = __shfl_up_sync(0xFFFFFFFFu, v, o);
        if (lane >= o) v += t;
    }
    if (lane == 31) wsum[wid] = v;
    __syncthreads();
    if (wid == 0) {
        int t = wsum[lane];
#pragma unroll
        for (int o = 1; o < 32; o <<= 1) {
            int u = __shfl_up_sync(0xFFFFFFFFu, t, o);
            if (lane >= o) t += u;
        }
        wsum[lane] = t;
    }
    __syncthreads();
    int pre = v - myv + (wid > 0 ? wsum[wid - 1] : 0);
    int g = pre >> 16;
    int e = pre & 0xFFFF;

    int vals[4];
#pragma unroll
    for (int j = 0; j < 4; ++j) {
        int kp = -1;
        if (k[j] > T)       { kp = g + min(e, Rfin); ++g; }
        else if (k[j] == T) { if (e < Rfin) kp = g + e; ++e; }
        vals[j] = kp;
    }
    int4 op = { vals[0], vals[1], vals[2], vals[3] };
    ((int4*)(pos + b * NN))[tid] = op;
}

// ---------------------------------------------------------------------------
// Kernel 3: streaming compaction-gather. 32 tokens x D in two d-halves,
// 128x33 smem tile (17KB), float4 loads, conflict-free both directions.
// out written with __stcs (streaming, never re-read) to preserve token
// residency in L2 for the reverse-batch-order reads.
// grid: (NN/32=128, BB), block 256.
// ---------------------------------------------------------------------------
__global__ void __launch_bounds__(256)
gather_kernel(const float* __restrict__ tokens,
              const int* __restrict__ pos,
              float* __restrict__ out)
{
    __shared__ float tile[128][33];
    __shared__ int   spos[32];

    const int tid = threadIdx.x;
    const int b   = (BB - 1) - blockIdx.y;    // hottest-in-L2 batches first
    const int n0  = blockIdx.x * 32;

    if (tid < 32) spos[tid] = pos[b * NN + n0 + tid];

    const int f  = tid & 7;                   // float4 slot (4 tokens)
    const int d0 = tid >> 3;                  // 0..31
    const float* base = tokens + (size_t)b * DD * NN + n0 + f * 4;
    float* ob = out + (size_t)b * KK * DD;

    const int kk2 = tid >> 7;                 // which of 2 rows this thread writes
    const int c   = tid & 127;                // column within 128-wide half

#pragma unroll
    for (int h = 0; h < 2; ++h) {
        __syncthreads();                      // tile reuse guard (and spos vis)
#pragma unroll
        for (int j = 0; j < 4; ++j) {         // 4 independent 16B LDGs
            int d = d0 + j * 32;              // local d within half
            float4 v = *(const float4*)(base + (size_t)(h * 128 + d) * NN);
            tile[d][f * 4 + 0] = v.x;
            tile[d][f * 4 + 1] = v.y;
            tile[d][f * 4 + 2] = v.z;
            tile[d][f * 4 + 3] = v.w;
        }
        __syncthreads();
#pragma unroll
        for (int pair = 0; pair < 16; ++pair) {
            int kk = pair * 2 + kk2;
            int p  = spos[kk];
            if (p >= 0)
                __stcs(&ob[(size_t)p * DD + h * 128 + c], tile[c][kk]);
        }
    }
}

// ---------------------------------------------------------------------------
extern "C" void kernel_launch(void* const* d_in, const int* in_sizes, int n_in,
                              void* d_out, int out_size)
{
    const float* tokens = (const float*)d_in[0];
    const float* norm_w = (const float*)d_in[1];
    // d_in[2] = norm_b (order-irrelevant constant shift)
    const float* fc_w   = (const float*)d_in[3];
    // d_in[4] = fc_b   (order-irrelevant constant shift)
    float* out = (float*)d_out;

    unsigned* keys;
    int* pos;
    cudaGetSymbolAddress((void**)&keys, g_keys);
    cudaGetSymbolAddress((void**)&pos,  g_pos);

    score_kernel<<<dim3(NN / 128, BB), 256>>>(tokens, norm_w, fc_w, keys);
    select_kernel<<<BB, 1024>>>(keys, pos);
    gather_kernel<<<dim3(NN / 32, BB), 256>>>(tokens, pos, out);
}